// round 11
// baseline (speedup 1.0000x reference)
#include <cuda_runtime.h>
#include <cuda_fp16.h>
#include <cstdint>
#include <math.h>

// Problem constants
#define BATCH 4
#define T 4096
#define D 512
#define CHK 128
#define NQC 32
#define WKEYS 384               // decay^256/(1-decay) ~ 8e-5 tail (validated)
#define MTOT 16384
#define XN (BATCH * T * D)
#define WN (D * D)              // 262144 = 2^18

// Scratch (all fp16)
__device__ __align__(16) __half g_xh[XN];
__device__ __align__(16) __half g_wh[4 * WN];
__device__ __align__(16) __half g_q [XN];
__device__ __align__(16) __half g_k [XN];
__device__ __align__(16) __half g_vT[BATCH * D * T];   // V transposed: [b][d][t]
__device__ __align__(16) __half g_ws[BATCH * NQC * CHK * WKEYS];
__device__ __align__(16) __half g_r [XN];

// ---------------------------------------------------------------------------
// helpers
// ---------------------------------------------------------------------------
__device__ __forceinline__ uint32_t f2h2(float x, float y) {
    __half2 h = __floats2half2_rn(x, y);
    return *(uint32_t*)&h;
}
__device__ __forceinline__ uint32_t smem_u32(const void* p) {
    uint32_t a;
    asm("{ .reg .u64 t; cvta.to.shared.u64 t, %1; cvt.u32.u64 %0, t; }"
        : "=r"(a) : "l"(p));
    return a;
}
__device__ __forceinline__ void mma16(float* c, const uint32_t* a,
                                      uint32_t b0, uint32_t b1) {
    asm volatile(
        "mma.sync.aligned.m16n8k16.row.col.f32.f16.f16.f32 "
        "{%0,%1,%2,%3}, {%4,%5,%6,%7}, {%8,%9}, {%0,%1,%2,%3};\n"
        : "+f"(c[0]), "+f"(c[1]), "+f"(c[2]), "+f"(c[3])
        : "r"(a[0]), "r"(a[1]), "r"(a[2]), "r"(a[3]), "r"(b0), "r"(b1));
}
#define LDSM4(d0, d1, d2, d3, a)                                        \
    asm volatile("ldmatrix.sync.aligned.m8n8.x4.shared.b16 "            \
        "{%0,%1,%2,%3}, [%4];"                                          \
        : "=r"(d0), "=r"(d1), "=r"(d2), "=r"(d3) : "r"(a))
#define CP_COMMIT() asm volatile("cp.async.commit_group;" ::: "memory")
#define CP_WAIT(n)  asm volatile("cp.async.wait_group %0;" :: "n"(n) : "memory")

// ---------------------------------------------------------------------------
// Smem tile: 128 rows x 64 halves (K-major, BK=64), row pitch 144 B (36 b32).
// LDSM phase banks: 36r mod 32 = 4r -> distinct over 8 consecutive rows ->
// conflict-free. Tile = 18432 B; stage (A+B) = 36864 B; 3 stages = 110592 B.
// CTA 128x128, 256 threads, 8 warps (2m x 4n), warp tile 64x32. 2 CTAs/SM.
// ---------------------------------------------------------------------------
#define NST 3
#define TILE_B 18432
#define STG_B  36864
#define SMEM_BYTES (NST * STG_B)   // 110592

// Four 16B cp.async per operand per thread (256 threads cover 128x64 halves).
__device__ __forceinline__ void cp_tile(uint32_t sb, const __half* __restrict__ g,
                                        int ld, int tid)
{
    const int r = tid >> 1, h = tid & 1;
    uint32_t dst = sb + (uint32_t)(r * 144 + 64 * h);
    const __half* src = g + (size_t)r * ld + 32 * h;
#pragma unroll
    for (int i = 0; i < 4; i++)
        asm volatile("cp.async.cg.shared.global [%0], [%1], 16;"
                     :: "r"(dst + (uint32_t)(16 * i)), "l"(src + 8 * i) : "memory");
}

// Fragment load + MMA for one k16 step at byte offset ko within the stage.
__device__ __forceinline__ void frag_ldsm(
    uint32_t as, uint32_t bs, uint32_t ko, int wm, int wn,
    uint32_t offA, uint32_t offB, uint32_t a[4][4], uint32_t b[4][2])
{
#pragma unroll
    for (int mi = 0; mi < 4; mi++)
        LDSM4(a[mi][0], a[mi][1], a[mi][2], a[mi][3],
              as + (uint32_t)(wm + mi * 16) * 144 + offA + ko);
#pragma unroll
    for (int j = 0; j < 2; j++) {
        uint32_t d0, d1, d2, d3;
        LDSM4(d0, d1, d2, d3, bs + (uint32_t)(wn + j * 16) * 144 + offB + ko);
        b[2 * j][0] = d0; b[2 * j][1] = d1;
        b[2 * j + 1][0] = d2; b[2 * j + 1][1] = d3;
    }
}
__device__ __forceinline__ void frag_mma(
    float (*acc)[4], uint32_t a[4][4], uint32_t b[4][2])
{
#pragma unroll
    for (int ni = 0; ni < 4; ni++)
#pragma unroll
        for (int mi = 0; mi < 4; mi++)
            mma16(acc[mi * 4 + ni], a[mi], b[ni][0], b[ni][1]);
}

// Core: acc += A[128,K] * B[128,K]^T (both K-major half), K = nkt*64.
__device__ __forceinline__ void gemm_core(
    const __half* __restrict__ A, int lda,
    const __half* __restrict__ B, int ldb,
    int nkt, float (*acc)[4],            // acc[mi*4+ni][4]
    uint32_t sb, int tid, int wm, int wn,
    uint32_t offA, uint32_t offB)
{
    cp_tile(sb, A, lda, tid);
    cp_tile(sb + TILE_B, B, ldb, tid);
    CP_COMMIT();
    if (nkt > 1) {
        cp_tile(sb + STG_B, A + 64, lda, tid);
        cp_tile(sb + STG_B + TILE_B, B + 64, ldb, tid);
        CP_COMMIT();
    }
    for (int it = 0; it < nkt; it++) {
        if (it + 1 < nkt) CP_WAIT(1); else CP_WAIT(0);
        __syncthreads();
        uint32_t as = sb + (uint32_t)(it % NST) * STG_B;
        uint32_t bs = as + TILE_B;
        uint32_t a[4][4], b[4][2];
        // k16 step 0: load frags, then issue next-stage prefetch (so LDSMs
        // aren't queued behind 8 cp.async at stage start), then MMA.
        frag_ldsm(as, bs, 0, wm, wn, offA, offB, a, b);
        if (it + 2 < nkt) {
            uint32_t s2 = sb + (uint32_t)((it + 2) % NST) * STG_B;
            cp_tile(s2, A + (it + 2) * 64, lda, tid);
            cp_tile(s2 + TILE_B, B + (it + 2) * 64, ldb, tid);
            CP_COMMIT();
        }
        frag_mma(acc, a, b);
#pragma unroll
        for (int ks = 1; ks < 4; ks++) {
            frag_ldsm(as, bs, (uint32_t)(ks * 32), wm, wn, offA, offB, a, b);
            frag_mma(acc, a, b);
        }
    }
}

#define GEMM_PROLOGUE()                                              \
    extern __shared__ uint32_t smbuf[];                              \
    float acc[16][4];                                                \
    _Pragma("unroll")                                                \
    for (int i = 0; i < 16; i++)                                     \
        _Pragma("unroll")                                            \
        for (int q = 0; q < 4; q++) acc[i][q] = 0.f;                 \
    const int tid = threadIdx.x;                                     \
    const int warp = tid >> 5, lane = tid & 31;                      \
    const int wm = (warp & 1) * 64, wn = (warp >> 1) * 32;           \
    const int g = lane >> 2, c = lane & 3, sel = lane >> 3;          \
    const uint32_t offA =                                            \
        (uint32_t)(((lane & 7) + 8 * (sel & 1)) * 144 + 16 * (sel >> 1)); \
    const uint32_t offB =                                            \
        (uint32_t)(((lane & 7) + 8 * (sel >> 1)) * 144 + 16 * (sel & 1)); \
    const uint32_t sb = smem_u32(smbuf);

// ---------------------------------------------------------------------------
// Kernel 0: convert x + weights to half.
// ---------------------------------------------------------------------------
__global__ __launch_bounds__(256) void prep(
    const float* __restrict__ x,
    const float* __restrict__ Wq, const float* __restrict__ Wk,
    const float* __restrict__ Wv, const float* __restrict__ Wo)
{
    int i = (blockIdx.x * 256 + threadIdx.x) * 8;
    const float* src;
    __half* dst;
    int off;
    if (i < XN) { src = x; dst = g_xh; off = i; }
    else {
        int j = i - XN;
        int wi = j >> 18;
        off = j & (WN - 1);
        src = (wi == 0) ? Wq : (wi == 1) ? Wk : (wi == 2) ? Wv : Wo;
        dst = g_wh + (wi << 18);
    }
    float4 a = *(const float4*)(src + off);
    float4 b = *(const float4*)(src + off + 4);
    uint4 o;
    o.x = f2h2(a.x, a.y); o.y = f2h2(a.z, a.w);
    o.z = f2h2(b.x, b.y); o.w = f2h2(b.z, b.w);
    *(uint4*)(dst + off) = o;
}

// ---------------------------------------------------------------------------
// Kernel 1: QKV. z=0 -> Q, z=1 -> K (row-major half), z=2 -> V transposed.
// ---------------------------------------------------------------------------
__global__ __launch_bounds__(256, 2) void qkv_gemm()
{
    GEMM_PROLOGUE();
    const int z = blockIdx.z;
    const int row0 = blockIdx.y * 128, col0 = blockIdx.x * 128;
    const __half* A = g_xh + (size_t)row0 * D;
    const __half* B = g_wh + (size_t)z * WN + (size_t)col0 * D;

    gemm_core(A, D, B, D, D / 64, acc, sb, tid, wm, wn, offA, offB);

    if (z < 2) {
        __half* Cp = ((z == 0) ? g_q : g_k) + (size_t)row0 * D + col0;
#pragma unroll
        for (int mi = 0; mi < 4; mi++)
#pragma unroll
            for (int ni = 0; ni < 4; ni++) {
                int row = wm + mi * 16 + g;
                int col = wn + ni * 8 + 2 * c;
                const float* v = acc[mi * 4 + ni];
                *(__half2*)&Cp[(size_t)row * D + col] = __floats2half2_rn(v[0], v[1]);
                *(__half2*)&Cp[(size_t)(row + 8) * D + col] = __floats2half2_rn(v[2], v[3]);
            }
    } else {
        const int b = row0 >> 12;
        const int t0 = row0 & (T - 1);
#pragma unroll
        for (int mi = 0; mi < 4; mi++)
#pragma unroll
            for (int ni = 0; ni < 4; ni++) {
                int t = t0 + wm + mi * 16 + g;
                int col = col0 + wn + ni * 8 + 2 * c;
                const float* v = acc[mi * 4 + ni];
                __half* base0 = g_vT + ((size_t)b * D + col) * T;
                __half* base1 = base0 + T;
                base0[t]     = __float2half_rn(v[0]);
                base1[t]     = __float2half_rn(v[1]);
                base0[t + 8] = __float2half_rn(v[2]);
                base1[t + 8] = __float2half_rn(v[3]);
            }
    }
}

// ---------------------------------------------------------------------------
// Kernel 2: banded scores + decay weights -> g_ws (half). Decay via smem table.
// ---------------------------------------------------------------------------
__global__ __launch_bounds__(256, 2) void scores_gemm(const float* __restrict__ decay_logit)
{
    const int bid = blockIdx.y;
    const int b = bid >> 5, qc = bid & 31;
    const int col0 = blockIdx.x * 128;
    const int kvalid = T - qc * CHK;
    if (col0 >= kvalid) return;

    GEMM_PROLOGUE();
    const __half* A = g_q + (size_t)(b * T + qc * CHK) * D;
    const __half* B = g_k + (size_t)(b * T + qc * CHK + col0) * D;

    gemm_core(A, D, B, D, D / 64, acc, sb, tid, wm, wn, offA, offB);

    __syncthreads();
    float* tbl = (float*)smbuf;
    {
        const float dl = *decay_logit;
        const float l2d = log2f(1.f / (1.f + expf(-dl)));
        for (int i = tid; i < WKEYS; i += 256)
            tbl[i] = exp2f((float)i * l2d);
    }
    __syncthreads();

    __half* WS = g_ws + (size_t)(b * NQC + qc) * CHK * WKEYS;
#pragma unroll
    for (int mi = 0; mi < 4; mi++)
#pragma unroll
        for (int ni = 0; ni < 4; ni++) {
            const float* v = acc[mi * 4 + ni];
#pragma unroll
            for (int hh = 0; hh < 2; hh++) {
                int ti = wm + mi * 16 + g + hh * 8;
                float v0, v1;
#pragma unroll
                for (int e = 0; e < 2; e++) {
                    int jj = col0 + wn + ni * 8 + 2 * c + e;
                    int diff = jj - ti;
                    float w = (diff > 0) ? tbl[diff - 1] : 0.f;
                    float r = v[hh * 2 + e] * w;
                    if (e == 0) v0 = r; else v1 = r;
                }
                int jj0 = col0 + wn + ni * 8 + 2 * c;
                *(__half2*)&WS[(size_t)ti * WKEYS + jj0] = __floats2half2_rn(v0, v1);
            }
        }
}

// ---------------------------------------------------------------------------
// Kernel 3: retrieved = WS @ V_window (NT against g_vT) -> g_r (half).
// keff is a multiple of 128 -> divisible by 64.
// ---------------------------------------------------------------------------
__global__ __launch_bounds__(256, 2) void retrv_gemm()
{
    GEMM_PROLOGUE();
    const int bid = blockIdx.y;
    const int b = bid >> 5, qc = bid & 31;
    const int col0 = blockIdx.x * 128;
    const int kvalid = T - qc * CHK;
    const int keff = (kvalid < WKEYS) ? kvalid : WKEYS;
    const int nkt = keff / 64;

    const __half* A = g_ws + (size_t)(b * NQC + qc) * CHK * WKEYS;
    const __half* B = g_vT + ((size_t)b * D + col0) * T + qc * CHK;

    gemm_core(A, WKEYS, B, T, nkt, acc, sb, tid, wm, wn, offA, offB);

    __half* Cp = g_r + (size_t)(b * T + qc * CHK) * D + col0;
#pragma unroll
    for (int mi = 0; mi < 4; mi++)
#pragma unroll
        for (int ni = 0; ni < 4; ni++) {
            int row = wm + mi * 16 + g;
            int col = wn + ni * 8 + 2 * c;
            const float* v = acc[mi * 4 + ni];
            *(__half2*)&Cp[(size_t)row * D + col] = __floats2half2_rn(v[0], v[1]);
            *(__half2*)&Cp[(size_t)(row + 8) * D + col] = __floats2half2_rn(v[2], v[3]);
        }
}

// ---------------------------------------------------------------------------
// Kernel 4: out = (R @ Wo^T) * out_scale   (float output)
// ---------------------------------------------------------------------------
__global__ __launch_bounds__(256, 2) void out_gemm(
    const float* __restrict__ out_scale,
    float* __restrict__ out)
{
    GEMM_PROLOGUE();
    const int row0 = blockIdx.y * 128, col0 = blockIdx.x * 128;
    const __half* A = g_r + (size_t)row0 * D;
    const __half* B = g_wh + 3 * WN + (size_t)col0 * D;

    gemm_core(A, D, B, D, D / 64, acc, sb, tid, wm, wn, offA, offB);

    const float sc = *out_scale;
    float* Cp = out + (size_t)row0 * D + col0;
#pragma unroll
    for (int mi = 0; mi < 4; mi++)
#pragma unroll
        for (int ni = 0; ni < 4; ni++) {
            int row = wm + mi * 16 + g;
            int col = wn + ni * 8 + 2 * c;
            const float* v = acc[mi * 4 + ni];
            *(float2*)&Cp[(size_t)row * D + col] = make_float2(v[0] * sc, v[1] * sc);
            *(float2*)&Cp[(size_t)(row + 8) * D + col] = make_float2(v[2] * sc, v[3] * sc);
        }
}

// ---------------------------------------------------------------------------
extern "C" void kernel_launch(void* const* d_in, const int* in_sizes, int n_in,
                              void* d_out, int out_size)
{
    const float* x  = (const float*)d_in[0];
    const float* Wq = (const float*)d_in[1];
    const float* Wk = (const float*)d_in[2];
    const float* Wv = (const float*)d_in[3];
    const float* Wo = (const float*)d_in[4];
    const float* dl = (const float*)d_in[5];
    const float* os = (const float*)d_in[6];
    float* out = (float*)d_out;

    cudaFuncSetAttribute(qkv_gemm,    cudaFuncAttributeMaxDynamicSharedMemorySize, SMEM_BYTES);
    cudaFuncSetAttribute(scores_gemm, cudaFuncAttributeMaxDynamicSharedMemorySize, SMEM_BYTES);
    cudaFuncSetAttribute(retrv_gemm,  cudaFuncAttributeMaxDynamicSharedMemorySize, SMEM_BYTES);
    cudaFuncSetAttribute(out_gemm,    cudaFuncAttributeMaxDynamicSharedMemorySize, SMEM_BYTES);

    prep<<<(XN + 4 * WN) / (8 * 256), 256>>>(x, Wq, Wk, Wv, Wo);
    dim3 blk(256);
    qkv_gemm   <<<dim3(4, MTOT / 128, 3), blk, SMEM_BYTES>>>();
    scores_gemm<<<dim3(WKEYS / 128, BATCH * NQC), blk, SMEM_BYTES>>>(dl);
    retrv_gemm <<<dim3(4, BATCH * NQC), blk, SMEM_BYTES>>>();
    out_gemm   <<<dim3(4, MTOT / 128), blk, SMEM_BYTES>>>(os, out);
}

// round 12
// speedup vs baseline: 1.0137x; 1.0137x over previous
#include <cuda_runtime.h>
#include <cuda_fp16.h>
#include <cstdint>
#include <math.h>

// Problem constants
#define BATCH 4
#define T 4096
#define D 512
#define CHK 128
#define NQC 32
#define WKEYS 384               // decay^256/(1-decay) ~ 8e-5 tail (validated)
#define MTOT 16384
#define XN (BATCH * T * D)
#define WN (D * D)              // 262144 = 2^18

// Scratch (all fp16)
__device__ __align__(16) __half g_xh[XN];
__device__ __align__(16) __half g_wh[4 * WN];
__device__ __align__(16) __half g_q [XN];
__device__ __align__(16) __half g_k [XN];
__device__ __align__(16) __half g_vT[BATCH * D * T];   // V transposed: [b][d][t]
__device__ __align__(16) __half g_ws[BATCH * NQC * CHK * WKEYS];
__device__ __align__(16) __half g_r [XN];

// ---------------------------------------------------------------------------
// helpers
// ---------------------------------------------------------------------------
__device__ __forceinline__ uint32_t f2h2(float x, float y) {
    __half2 h = __floats2half2_rn(x, y);
    return *(uint32_t*)&h;
}
__device__ __forceinline__ uint32_t smem_u32(const void* p) {
    uint32_t a;
    asm("{ .reg .u64 t; cvta.to.shared.u64 t, %1; cvt.u32.u64 %0, t; }"
        : "=r"(a) : "l"(p));
    return a;
}
__device__ __forceinline__ void mma16(float* c, const uint32_t* a,
                                      uint32_t b0, uint32_t b1) {
    asm volatile(
        "mma.sync.aligned.m16n8k16.row.col.f32.f16.f16.f32 "
        "{%0,%1,%2,%3}, {%4,%5,%6,%7}, {%8,%9}, {%0,%1,%2,%3};\n"
        : "+f"(c[0]), "+f"(c[1]), "+f"(c[2]), "+f"(c[3])
        : "r"(a[0]), "r"(a[1]), "r"(a[2]), "r"(a[3]), "r"(b0), "r"(b1));
}
#define LDSM4(d0, d1, d2, d3, a)                                        \
    asm volatile("ldmatrix.sync.aligned.m8n8.x4.shared.b16 "            \
        "{%0,%1,%2,%3}, [%4];"                                          \
        : "=r"(d0), "=r"(d1), "=r"(d2), "=r"(d3) : "r"(a))
#define CP_COMMIT() asm volatile("cp.async.commit_group;" ::: "memory")
#define CP_WAIT(n)  asm volatile("cp.async.wait_group %0;" :: "n"(n) : "memory")

// ---------------------------------------------------------------------------
// Shared layout: K-major tiles, BK=32 halves, row pitch 80 B (20 b32).
// LDSM phase banks: 20r + off mod 32 distinct over 8 consecutive rows ->
// conflict-free.
// Config A (qkv/scores): CTA 128x128, 8 warps 2m x 4n, warp 64x32, 2 CTAs/SM.
//   Stage = A(10240) + B(10240) = 20 KB; 3 stages = 60 KB.
// Config B (retrv/out):  CTA 128x64, 8 warps 2m x 4n, warp 64x16, 3 CTAs/SM.
//   Stage = A(10240) + B(5120) = 15 KB; 3 stages = 45 KB.
// ---------------------------------------------------------------------------
#define NST 3
#define TILE_A 10240
#define TILE_B64 5120
#define STG_B  20480
#define STG_B2 15360
#define SMEM_BYTES  (NST * STG_B)    // 61440
#define SMEM_BYTES2 (NST * STG_B2)   // 46080

// 128-row x 32-half tile: two 16B cp.async per thread (256 threads).
__device__ __forceinline__ void cp_tile(uint32_t sb, const __half* __restrict__ g,
                                        int ld, int tid)
{
    const int r = tid >> 1, h = tid & 1;
    uint32_t dst = sb + (uint32_t)(r * 80 + 16 * h);
    const __half* src = g + (size_t)r * ld + 8 * h;
    asm volatile("cp.async.cg.shared.global [%0], [%1], 16;"
                 :: "r"(dst), "l"(src) : "memory");
    asm volatile("cp.async.cg.shared.global [%0], [%1], 16;"
                 :: "r"(dst + 32), "l"(src + 16) : "memory");
}

// 64-row x 32-half tile: one 16B cp.async per thread.
__device__ __forceinline__ void cp_tile64(uint32_t sb, const __half* __restrict__ g,
                                          int ld, int tid)
{
    const int r = tid >> 2, q = tid & 3;
    uint32_t dst = sb + (uint32_t)(r * 80 + 16 * q);
    const __half* src = g + (size_t)r * ld + 8 * q;
    asm volatile("cp.async.cg.shared.global [%0], [%1], 16;"
                 :: "r"(dst), "l"(src) : "memory");
}

// ---------------------------------------------------------------------------
// Core A: acc[16][4] += A[128,K] * B[128,K]^T, warp tile 64x32.
// ---------------------------------------------------------------------------
__device__ __forceinline__ void gemm_core(
    const __half* __restrict__ A, int lda,
    const __half* __restrict__ B, int ldb,
    int nkt, float (*acc)[4],
    uint32_t sb, int tid, int wm, int wn,
    uint32_t offA, uint32_t offB)
{
    cp_tile(sb, A, lda, tid);
    cp_tile(sb + TILE_A, B, ldb, tid);
    CP_COMMIT();
    if (nkt > 1) {
        cp_tile(sb + STG_B, A + 32, lda, tid);
        cp_tile(sb + STG_B + TILE_A, B + 32, ldb, tid);
        CP_COMMIT();
    }
    for (int it = 0; it < nkt; it++) {
        if (it + 1 < nkt) CP_WAIT(1); else CP_WAIT(0);
        __syncthreads();
        if (it + 2 < nkt) {
            uint32_t s2 = sb + (uint32_t)((it + 2) % NST) * STG_B;
            cp_tile(s2, A + (it + 2) * 32, lda, tid);
            cp_tile(s2 + TILE_A, B + (it + 2) * 32, ldb, tid);
            CP_COMMIT();
        }
        uint32_t as = sb + (uint32_t)(it % NST) * STG_B;
        uint32_t bs = as + TILE_A;
#pragma unroll
        for (int ks = 0; ks < 2; ks++) {
            const uint32_t ko = (uint32_t)(ks * 32);
            uint32_t a[4][4], b[4][2];
#pragma unroll
            for (int mi = 0; mi < 4; mi++)
                LDSM4(a[mi][0], a[mi][1], a[mi][2], a[mi][3],
                      as + (uint32_t)(wm + mi * 16) * 80 + offA + ko);
#pragma unroll
            for (int j = 0; j < 2; j++) {
                uint32_t d0, d1, d2, d3;
                LDSM4(d0, d1, d2, d3,
                      bs + (uint32_t)(wn + j * 16) * 80 + offB + ko);
                b[2 * j][0] = d0; b[2 * j][1] = d1;
                b[2 * j + 1][0] = d2; b[2 * j + 1][1] = d3;
            }
#pragma unroll
            for (int ni = 0; ni < 4; ni++)
#pragma unroll
                for (int mi = 0; mi < 4; mi++)
                    mma16(acc[mi * 4 + ni], a[mi], b[ni][0], b[ni][1]);
        }
    }
}

// ---------------------------------------------------------------------------
// Core B: acc[8][4] += A[128,K] * B[64,K]^T, warp tile 64x16 (high occupancy).
// ---------------------------------------------------------------------------
__device__ __forceinline__ void gemm_core64(
    const __half* __restrict__ A, int lda,
    const __half* __restrict__ B, int ldb,
    int nkt, float (*acc)[4],
    uint32_t sb, int tid, int wm, int wn,
    uint32_t offA, uint32_t offB)
{
    cp_tile(sb, A, lda, tid);
    cp_tile64(sb + TILE_A, B, ldb, tid);
    CP_COMMIT();
    if (nkt > 1) {
        cp_tile(sb + STG_B2, A + 32, lda, tid);
        cp_tile64(sb + STG_B2 + TILE_A, B + 32, ldb, tid);
        CP_COMMIT();
    }
    for (int it = 0; it < nkt; it++) {
        if (it + 1 < nkt) CP_WAIT(1); else CP_WAIT(0);
        __syncthreads();
        if (it + 2 < nkt) {
            uint32_t s2 = sb + (uint32_t)((it + 2) % NST) * STG_B2;
            cp_tile(s2, A + (it + 2) * 32, lda, tid);
            cp_tile64(s2 + TILE_A, B + (it + 2) * 32, ldb, tid);
            CP_COMMIT();
        }
        uint32_t as = sb + (uint32_t)(it % NST) * STG_B2;
        uint32_t bs = as + TILE_A;
#pragma unroll
        for (int ks = 0; ks < 2; ks++) {
            const uint32_t ko = (uint32_t)(ks * 32);
            uint32_t a[4][4], b0, b1, b2, b3;
#pragma unroll
            for (int mi = 0; mi < 4; mi++)
                LDSM4(a[mi][0], a[mi][1], a[mi][2], a[mi][3],
                      as + (uint32_t)(wm + mi * 16) * 80 + offA + ko);
            LDSM4(b0, b1, b2, b3, bs + (uint32_t)wn * 80 + offB + ko);
#pragma unroll
            for (int mi = 0; mi < 4; mi++) {
                mma16(acc[mi * 2 + 0], a[mi], b0, b1);
                mma16(acc[mi * 2 + 1], a[mi], b2, b3);
            }
        }
    }
}

#define PROLOGUE_COMMON()                                            \
    extern __shared__ uint32_t smbuf[];                              \
    const int tid = threadIdx.x;                                     \
    const int warp = tid >> 5, lane = tid & 31;                      \
    const int g = lane >> 2, c = lane & 3, sel = lane >> 3;          \
    const uint32_t offA =                                            \
        (uint32_t)(((lane & 7) + 8 * (sel & 1)) * 80 + 16 * (sel >> 1)); \
    const uint32_t offB =                                            \
        (uint32_t)(((lane & 7) + 8 * (sel >> 1)) * 80 + 16 * (sel & 1)); \
    const uint32_t sb = smem_u32(smbuf);

#define GEMM_PROLOGUE()                                              \
    PROLOGUE_COMMON();                                               \
    const int wm = (warp & 1) * 64, wn = (warp >> 1) * 32;           \
    float acc[16][4];                                                \
    _Pragma("unroll")                                                \
    for (int i = 0; i < 16; i++)                                     \
        _Pragma("unroll")                                            \
        for (int q = 0; q < 4; q++) acc[i][q] = 0.f;

#define GEMM_PROLOGUE64()                                            \
    PROLOGUE_COMMON();                                               \
    const int wm = (warp & 1) * 64, wn = (warp >> 1) * 16;           \
    float acc[8][4];                                                 \
    _Pragma("unroll")                                                \
    for (int i = 0; i < 8; i++)                                      \
        _Pragma("unroll")                                            \
        for (int q = 0; q < 4; q++) acc[i][q] = 0.f;

// ---------------------------------------------------------------------------
// Kernel 0: convert x + weights to half.
// ---------------------------------------------------------------------------
__global__ __launch_bounds__(256) void prep(
    const float* __restrict__ x,
    const float* __restrict__ Wq, const float* __restrict__ Wk,
    const float* __restrict__ Wv, const float* __restrict__ Wo)
{
    int i = (blockIdx.x * 256 + threadIdx.x) * 8;
    const float* src;
    __half* dst;
    int off;
    if (i < XN) { src = x; dst = g_xh; off = i; }
    else {
        int j = i - XN;
        int wi = j >> 18;
        off = j & (WN - 1);
        src = (wi == 0) ? Wq : (wi == 1) ? Wk : (wi == 2) ? Wv : Wo;
        dst = g_wh + (wi << 18);
    }
    float4 a = *(const float4*)(src + off);
    float4 b = *(const float4*)(src + off + 4);
    uint4 o;
    o.x = f2h2(a.x, a.y); o.y = f2h2(a.z, a.w);
    o.z = f2h2(b.x, b.y); o.w = f2h2(b.z, b.w);
    *(uint4*)(dst + off) = o;
}

// ---------------------------------------------------------------------------
// Kernel 1: QKV. z=0 -> Q, z=1 -> K (row-major half), z=2 -> V transposed.
// ---------------------------------------------------------------------------
__global__ __launch_bounds__(256, 2) void qkv_gemm()
{
    GEMM_PROLOGUE();
    const int z = blockIdx.z;
    const int row0 = blockIdx.y * 128, col0 = blockIdx.x * 128;
    const __half* A = g_xh + (size_t)row0 * D;
    const __half* B = g_wh + (size_t)z * WN + (size_t)col0 * D;

    gemm_core(A, D, B, D, D / 32, acc, sb, tid, wm, wn, offA, offB);

    if (z < 2) {
        __half* Cp = ((z == 0) ? g_q : g_k) + (size_t)row0 * D + col0;
#pragma unroll
        for (int mi = 0; mi < 4; mi++)
#pragma unroll
            for (int ni = 0; ni < 4; ni++) {
                int row = wm + mi * 16 + g;
                int col = wn + ni * 8 + 2 * c;
                const float* v = acc[mi * 4 + ni];
                *(__half2*)&Cp[(size_t)row * D + col] = __floats2half2_rn(v[0], v[1]);
                *(__half2*)&Cp[(size_t)(row + 8) * D + col] = __floats2half2_rn(v[2], v[3]);
            }
    } else {
        const int b = row0 >> 12;
        const int t0 = row0 & (T - 1);
#pragma unroll
        for (int mi = 0; mi < 4; mi++)
#pragma unroll
            for (int ni = 0; ni < 4; ni++) {
                int t = t0 + wm + mi * 16 + g;
                int col = col0 + wn + ni * 8 + 2 * c;
                const float* v = acc[mi * 4 + ni];
                __half* base0 = g_vT + ((size_t)b * D + col) * T;
                __half* base1 = base0 + T;
                base0[t]     = __float2half_rn(v[0]);
                base1[t]     = __float2half_rn(v[1]);
                base0[t + 8] = __float2half_rn(v[2]);
                base1[t + 8] = __float2half_rn(v[3]);
            }
    }
}

// ---------------------------------------------------------------------------
// Kernel 2: banded scores + decay weights -> g_ws (half). Decay via smem table.
// ---------------------------------------------------------------------------
__global__ __launch_bounds__(256, 2) void scores_gemm(const float* __restrict__ decay_logit)
{
    const int bid = blockIdx.y;
    const int b = bid >> 5, qc = bid & 31;
    const int col0 = blockIdx.x * 128;
    const int kvalid = T - qc * CHK;
    if (col0 >= kvalid) return;

    GEMM_PROLOGUE();
    const __half* A = g_q + (size_t)(b * T + qc * CHK) * D;
    const __half* B = g_k + (size_t)(b * T + qc * CHK + col0) * D;

    gemm_core(A, D, B, D, D / 32, acc, sb, tid, wm, wn, offA, offB);

    __syncthreads();
    float* tbl = (float*)smbuf;
    {
        const float dl = *decay_logit;
        const float l2d = log2f(1.f / (1.f + expf(-dl)));
        for (int i = tid; i < WKEYS; i += 256)
            tbl[i] = exp2f((float)i * l2d);
    }
    __syncthreads();

    __half* WS = g_ws + (size_t)(b * NQC + qc) * CHK * WKEYS;
#pragma unroll
    for (int mi = 0; mi < 4; mi++)
#pragma unroll
        for (int ni = 0; ni < 4; ni++) {
            const float* v = acc[mi * 4 + ni];
#pragma unroll
            for (int hh = 0; hh < 2; hh++) {
                int ti = wm + mi * 16 + g + hh * 8;
                float v0, v1;
#pragma unroll
                for (int e = 0; e < 2; e++) {
                    int jj = col0 + wn + ni * 8 + 2 * c + e;
                    int diff = jj - ti;
                    float w = (diff > 0) ? tbl[diff - 1] : 0.f;
                    float r = v[hh * 2 + e] * w;
                    if (e == 0) v0 = r; else v1 = r;
                }
                int jj0 = col0 + wn + ni * 8 + 2 * c;
                *(__half2*)&WS[(size_t)ti * WKEYS + jj0] = __floats2half2_rn(v0, v1);
            }
        }
}

// ---------------------------------------------------------------------------
// Kernel 3: retrieved = WS @ V_window (NT against g_vT) -> g_r (half).
// High-occupancy config: CTA 128x64, 3 CTAs/SM.
// ---------------------------------------------------------------------------
__global__ __launch_bounds__(256, 3) void retrv_gemm()
{
    GEMM_PROLOGUE64();
    const int bid = blockIdx.y;
    const int b = bid >> 5, qc = bid & 31;
    const int col0 = blockIdx.x * 64;
    const int kvalid = T - qc * CHK;
    const int keff = (kvalid < WKEYS) ? kvalid : WKEYS;
    const int nkt = keff / 32;

    const __half* A = g_ws + (size_t)(b * NQC + qc) * CHK * WKEYS;
    const __half* B = g_vT + ((size_t)b * D + col0) * T + qc * CHK;

    gemm_core64(A, WKEYS, B, T, nkt, acc, sb, tid, wm, wn, offA, offB);

    __half* Cp = g_r + (size_t)(b * T + qc * CHK) * D + col0;
#pragma unroll
    for (int mi = 0; mi < 4; mi++)
#pragma unroll
        for (int ni = 0; ni < 2; ni++) {
            int row = wm + mi * 16 + g;
            int col = wn + ni * 8 + 2 * c;
            const float* v = acc[mi * 2 + ni];
            *(__half2*)&Cp[(size_t)row * D + col] = __floats2half2_rn(v[0], v[1]);
            *(__half2*)&Cp[(size_t)(row + 8) * D + col] = __floats2half2_rn(v[2], v[3]);
        }
}

// ---------------------------------------------------------------------------
// Kernel 4: out = (R @ Wo^T) * out_scale  (float output).
// High-occupancy config: CTA 128x64, 3 CTAs/SM.
// ---------------------------------------------------------------------------
__global__ __launch_bounds__(256, 3) void out_gemm(
    const float* __restrict__ out_scale,
    float* __restrict__ out)
{
    GEMM_PROLOGUE64();
    const int row0 = blockIdx.y * 128, col0 = blockIdx.x * 64;
    const __half* A = g_r + (size_t)row0 * D;
    const __half* B = g_wh + 3 * WN + (size_t)col0 * D;

    gemm_core64(A, D, B, D, D / 32, acc, sb, tid, wm, wn, offA, offB);

    const float sc = *out_scale;
    float* Cp = out + (size_t)row0 * D + col0;
#pragma unroll
    for (int mi = 0; mi < 4; mi++)
#pragma unroll
        for (int ni = 0; ni < 2; ni++) {
            int row = wm + mi * 16 + g;
            int col = wn + ni * 8 + 2 * c;
            const float* v = acc[mi * 2 + ni];
            *(float2*)&Cp[(size_t)row * D + col] = make_float2(v[0] * sc, v[1] * sc);
            *(float2*)&Cp[(size_t)(row + 8) * D + col] = make_float2(v[2] * sc, v[3] * sc);
        }
}

// ---------------------------------------------------------------------------
extern "C" void kernel_launch(void* const* d_in, const int* in_sizes, int n_in,
                              void* d_out, int out_size)
{
    const float* x  = (const float*)d_in[0];
    const float* Wq = (const float*)d_in[1];
    const float* Wk = (const float*)d_in[2];
    const float* Wv = (const float*)d_in[3];
    const float* Wo = (const float*)d_in[4];
    const float* dl = (const float*)d_in[5];
    const float* os = (const float*)d_in[6];
    float* out = (float*)d_out;

    cudaFuncSetAttribute(qkv_gemm,    cudaFuncAttributeMaxDynamicSharedMemorySize, SMEM_BYTES);
    cudaFuncSetAttribute(scores_gemm, cudaFuncAttributeMaxDynamicSharedMemorySize, SMEM_BYTES);
    cudaFuncSetAttribute(retrv_gemm,  cudaFuncAttributeMaxDynamicSharedMemorySize, SMEM_BYTES2);
    cudaFuncSetAttribute(out_gemm,    cudaFuncAttributeMaxDynamicSharedMemorySize, SMEM_BYTES2);

    prep<<<(XN + 4 * WN) / (8 * 256), 256>>>(x, Wq, Wk, Wv, Wo);
    dim3 blk(256);
    qkv_gemm   <<<dim3(4, MTOT / 128, 3), blk, SMEM_BYTES>>>();
    scores_gemm<<<dim3(WKEYS / 128, BATCH * NQC), blk, SMEM_BYTES>>>(dl);
    retrv_gemm <<<dim3(8, BATCH * NQC), blk, SMEM_BYTES2>>>();
    out_gemm   <<<dim3(8, MTOT / 128), blk, SMEM_BYTES2>>>(os, out);
}

// round 13
// speedup vs baseline: 1.0411x; 1.0271x over previous
#include <cuda_runtime.h>
#include <cuda_fp16.h>
#include <cstdint>
#include <math.h>

// Problem constants
#define BATCH 4
#define T 4096
#define D 512
#define CHK 128
#define NQC 32
#define WKEYS 384               // decay^256/(1-decay) ~ 8e-5 tail (validated)
#define MTOT 16384
#define XN (BATCH * T * D)
#define WN (D * D)              // 262144 = 2^18

// Scratch (all fp16)
__device__ __align__(16) __half g_xh[XN];
__device__ __align__(16) __half g_wh[4 * WN];
__device__ __align__(16) __half g_q [XN];
__device__ __align__(16) __half g_k [XN];
__device__ __align__(16) __half g_vT[BATCH * D * T];   // V transposed: [b][d][t]
__device__ __align__(16) __half g_ws[BATCH * NQC * CHK * WKEYS];
__device__ __align__(16) __half g_r [XN];

// ---------------------------------------------------------------------------
// helpers
// ---------------------------------------------------------------------------
__device__ __forceinline__ uint32_t f2h2(float x, float y) {
    __half2 h = __floats2half2_rn(x, y);
    return *(uint32_t*)&h;
}
__device__ __forceinline__ uint32_t smem_u32(const void* p) {
    uint32_t a;
    asm("{ .reg .u64 t; cvta.to.shared.u64 t, %1; cvt.u32.u64 %0, t; }"
        : "=r"(a) : "l"(p));
    return a;
}
__device__ __forceinline__ void mma16(float* c, const uint32_t* a,
                                      uint32_t b0, uint32_t b1) {
    asm volatile(
        "mma.sync.aligned.m16n8k16.row.col.f32.f16.f16.f32 "
        "{%0,%1,%2,%3}, {%4,%5,%6,%7}, {%8,%9}, {%0,%1,%2,%3};\n"
        : "+f"(c[0]), "+f"(c[1]), "+f"(c[2]), "+f"(c[3])
        : "r"(a[0]), "r"(a[1]), "r"(a[2]), "r"(a[3]), "r"(b0), "r"(b1));
}
#define LDSM4(d0, d1, d2, d3, a)                                        \
    asm volatile("ldmatrix.sync.aligned.m8n8.x4.shared.b16 "            \
        "{%0,%1,%2,%3}, [%4];"                                          \
        : "=r"(d0), "=r"(d1), "=r"(d2), "=r"(d3) : "r"(a))
#define CP_COMMIT() asm volatile("cp.async.commit_group;" ::: "memory")
#define CP_WAIT(n)  asm volatile("cp.async.wait_group %0;" :: "n"(n) : "memory")

// ---------------------------------------------------------------------------
// Smem tile: 128 rows x 32 halves (K-major, BK=32), row pitch 80 B (20 b32).
// LDSM phase banks: 20r + off mod 32 distinct over 8 consecutive rows ->
// conflict-free. Tile = 10240 B; stage (A+B) = 20 KB; 3 stages = 60 KB dyn.
// CTA 128x128, 256 threads, 8 warps (2m x 4n), warp tile 64x32. 2 CTAs/SM.
// Warp phase-skew: odd warps run the two ks-halves in reverse order so
// LDSM bursts of half the warps overlap MMA bursts of the other half.
// ---------------------------------------------------------------------------
#define NST 3
#define TILE_B 10240
#define STG_B  20480
#define SMEM_BYTES (NST * STG_B)   // 61440

// Two 16B cp.async per operand per thread (256 threads cover 128x32 halves).
__device__ __forceinline__ void cp_tile(uint32_t sb, const __half* __restrict__ g,
                                        int ld, int tid)
{
    const int r = tid >> 1, h = tid & 1;
    uint32_t dst = sb + (uint32_t)(r * 80 + 16 * h);
    const __half* src = g + (size_t)r * ld + 8 * h;
    asm volatile("cp.async.cg.shared.global [%0], [%1], 16;"
                 :: "r"(dst), "l"(src) : "memory");
    asm volatile("cp.async.cg.shared.global [%0], [%1], 16;"
                 :: "r"(dst + 32), "l"(src + 16) : "memory");
}

// Core: acc += A[128,K] * B[128,K]^T (both K-major half), K = nkt*32.
__device__ __forceinline__ void gemm_core(
    const __half* __restrict__ A, int lda,
    const __half* __restrict__ B, int ldb,
    int nkt, float (*acc)[4],            // acc[mi*4+ni][4]
    uint32_t sb, int tid, int wm, int wn,
    uint32_t offA, uint32_t offB)
{
    const int wpar = (tid >> 5) & 1;     // warp parity for phase skew
    cp_tile(sb, A, lda, tid);
    cp_tile(sb + TILE_B, B, ldb, tid);
    CP_COMMIT();
    if (nkt > 1) {
        cp_tile(sb + STG_B, A + 32, lda, tid);
        cp_tile(sb + STG_B + TILE_B, B + 32, ldb, tid);
        CP_COMMIT();
    }
    for (int it = 0; it < nkt; it++) {
        if (it + 1 < nkt) CP_WAIT(1); else CP_WAIT(0);
        __syncthreads();
        if (it + 2 < nkt) {
            uint32_t s2 = sb + (uint32_t)((it + 2) % NST) * STG_B;
            cp_tile(s2, A + (it + 2) * 32, lda, tid);
            cp_tile(s2 + TILE_B, B + (it + 2) * 32, ldb, tid);
            CP_COMMIT();
        }
        uint32_t as = sb + (uint32_t)(it % NST) * STG_B;
        uint32_t bs = as + TILE_B;
#pragma unroll
        for (int kss = 0; kss < 2; kss++) {
            const int ks = kss ^ wpar;               // phase skew
            const uint32_t ko = (uint32_t)(ks * 32);
            uint32_t a[4][4], b[4][2];
#pragma unroll
            for (int mi = 0; mi < 4; mi++)
                LDSM4(a[mi][0], a[mi][1], a[mi][2], a[mi][3],
                      as + (uint32_t)(wm + mi * 16) * 80 + offA + ko);
#pragma unroll
            for (int j = 0; j < 2; j++) {
                uint32_t d0, d1, d2, d3;
                LDSM4(d0, d1, d2, d3,
                      bs + (uint32_t)(wn + j * 16) * 80 + offB + ko);
                b[2 * j][0] = d0; b[2 * j][1] = d1;
                b[2 * j + 1][0] = d2; b[2 * j + 1][1] = d3;
            }
#pragma unroll
            for (int ni = 0; ni < 4; ni++)
#pragma unroll
                for (int mi = 0; mi < 4; mi++)
                    mma16(acc[mi * 4 + ni], a[mi], b[ni][0], b[ni][1]);
        }
    }
}

#define GEMM_PROLOGUE()                                              \
    extern __shared__ uint32_t smbuf[];                              \
    float acc[16][4];                                                \
    _Pragma("unroll")                                                \
    for (int i = 0; i < 16; i++)                                     \
        _Pragma("unroll")                                            \
        for (int q = 0; q < 4; q++) acc[i][q] = 0.f;                 \
    const int tid = threadIdx.x;                                     \
    const int warp = tid >> 5, lane = tid & 31;                      \
    const int wm = (warp & 1) * 64, wn = (warp >> 1) * 32;           \
    const int g = lane >> 2, c = lane & 3, sel = lane >> 3;          \
    const uint32_t offA =                                            \
        (uint32_t)(((lane & 7) + 8 * (sel & 1)) * 80 + 16 * (sel >> 1)); \
    const uint32_t offB =                                            \
        (uint32_t)(((lane & 7) + 8 * (sel >> 1)) * 80 + 16 * (sel & 1)); \
    const uint32_t sb = smem_u32(smbuf);

// ---------------------------------------------------------------------------
// Kernel 0: convert x + weights to half.
// ---------------------------------------------------------------------------
__global__ __launch_bounds__(256) void prep(
    const float* __restrict__ x,
    const float* __restrict__ Wq, const float* __restrict__ Wk,
    const float* __restrict__ Wv, const float* __restrict__ Wo)
{
    int i = (blockIdx.x * 256 + threadIdx.x) * 8;
    const float* src;
    __half* dst;
    int off;
    if (i < XN) { src = x; dst = g_xh; off = i; }
    else {
        int j = i - XN;
        int wi = j >> 18;
        off = j & (WN - 1);
        src = (wi == 0) ? Wq : (wi == 1) ? Wk : (wi == 2) ? Wv : Wo;
        dst = g_wh + (wi << 18);
    }
    float4 a = *(const float4*)(src + off);
    float4 b = *(const float4*)(src + off + 4);
    uint4 o;
    o.x = f2h2(a.x, a.y); o.y = f2h2(a.z, a.w);
    o.z = f2h2(b.x, b.y); o.w = f2h2(b.z, b.w);
    *(uint4*)(dst + off) = o;
}

// ---------------------------------------------------------------------------
// Kernel 1: QKV. z=0 -> Q, z=1 -> K (row-major half), z=2 -> V transposed.
// ---------------------------------------------------------------------------
__global__ __launch_bounds__(256, 2) void qkv_gemm()
{
    GEMM_PROLOGUE();
    const int z = blockIdx.z;
    const int row0 = blockIdx.y * 128, col0 = blockIdx.x * 128;
    const __half* A = g_xh + (size_t)row0 * D;
    const __half* B = g_wh + (size_t)z * WN + (size_t)col0 * D;

    gemm_core(A, D, B, D, D / 32, acc, sb, tid, wm, wn, offA, offB);

    if (z < 2) {
        __half* Cp = ((z == 0) ? g_q : g_k) + (size_t)row0 * D + col0;
#pragma unroll
        for (int mi = 0; mi < 4; mi++)
#pragma unroll
            for (int ni = 0; ni < 4; ni++) {
                int row = wm + mi * 16 + g;
                int col = wn + ni * 8 + 2 * c;
                const float* v = acc[mi * 4 + ni];
                *(__half2*)&Cp[(size_t)row * D + col] = __floats2half2_rn(v[0], v[1]);
                *(__half2*)&Cp[(size_t)(row + 8) * D + col] = __floats2half2_rn(v[2], v[3]);
            }
    } else {
        const int b = row0 >> 12;
        const int t0 = row0 & (T - 1);
#pragma unroll
        for (int mi = 0; mi < 4; mi++)
#pragma unroll
            for (int ni = 0; ni < 4; ni++) {
                int t = t0 + wm + mi * 16 + g;
                int col = col0 + wn + ni * 8 + 2 * c;
                const float* v = acc[mi * 4 + ni];
                __half* base0 = g_vT + ((size_t)b * D + col) * T;
                __half* base1 = base0 + T;
                base0[t]     = __float2half_rn(v[0]);
                base1[t]     = __float2half_rn(v[1]);
                base0[t + 8] = __float2half_rn(v[2]);
                base1[t + 8] = __float2half_rn(v[3]);
            }
    }
}

// ---------------------------------------------------------------------------
// Kernel 2: banded scores + decay weights -> g_ws (half). Decay via smem table.
// ---------------------------------------------------------------------------
__global__ __launch_bounds__(256, 2) void scores_gemm(const float* __restrict__ decay_logit)
{
    const int bid = blockIdx.y;
    const int b = bid >> 5, qc = bid & 31;
    const int col0 = blockIdx.x * 128;
    const int kvalid = T - qc * CHK;
    if (col0 >= kvalid) return;

    GEMM_PROLOGUE();
    const __half* A = g_q + (size_t)(b * T + qc * CHK) * D;
    const __half* B = g_k + (size_t)(b * T + qc * CHK + col0) * D;

    gemm_core(A, D, B, D, D / 32, acc, sb, tid, wm, wn, offA, offB);

    __syncthreads();
    float* tbl = (float*)smbuf;
    {
        const float dl = *decay_logit;
        const float l2d = log2f(1.f / (1.f + expf(-dl)));
        for (int i = tid; i < WKEYS; i += 256)
            tbl[i] = exp2f((float)i * l2d);
    }
    __syncthreads();

    __half* WS = g_ws + (size_t)(b * NQC + qc) * CHK * WKEYS;
#pragma unroll
    for (int mi = 0; mi < 4; mi++)
#pragma unroll
        for (int ni = 0; ni < 4; ni++) {
            const float* v = acc[mi * 4 + ni];
#pragma unroll
            for (int hh = 0; hh < 2; hh++) {
                int ti = wm + mi * 16 + g + hh * 8;
                float v0, v1;
#pragma unroll
                for (int e = 0; e < 2; e++) {
                    int jj = col0 + wn + ni * 8 + 2 * c + e;
                    int diff = jj - ti;
                    float w = (diff > 0) ? tbl[diff - 1] : 0.f;
                    float r = v[hh * 2 + e] * w;
                    if (e == 0) v0 = r; else v1 = r;
                }
                int jj0 = col0 + wn + ni * 8 + 2 * c;
                *(__half2*)&WS[(size_t)ti * WKEYS + jj0] = __floats2half2_rn(v0, v1);
            }
        }
}

// ---------------------------------------------------------------------------
// Kernel 3: retrieved = WS @ V_window (NT against g_vT) -> g_r (half).
// ---------------------------------------------------------------------------
__global__ __launch_bounds__(256, 2) void retrv_gemm()
{
    GEMM_PROLOGUE();
    const int bid = blockIdx.y;
    const int b = bid >> 5, qc = bid & 31;
    const int col0 = blockIdx.x * 128;
    const int kvalid = T - qc * CHK;
    const int keff = (kvalid < WKEYS) ? kvalid : WKEYS;
    const int nkt = keff / 32;

    const __half* A = g_ws + (size_t)(b * NQC + qc) * CHK * WKEYS;
    const __half* B = g_vT + ((size_t)b * D + col0) * T + qc * CHK;

    gemm_core(A, WKEYS, B, T, nkt, acc, sb, tid, wm, wn, offA, offB);

    __half* Cp = g_r + (size_t)(b * T + qc * CHK) * D + col0;
#pragma unroll
    for (int mi = 0; mi < 4; mi++)
#pragma unroll
        for (int ni = 0; ni < 4; ni++) {
            int row = wm + mi * 16 + g;
            int col = wn + ni * 8 + 2 * c;
            const float* v = acc[mi * 4 + ni];
            *(__half2*)&Cp[(size_t)row * D + col] = __floats2half2_rn(v[0], v[1]);
            *(__half2*)&Cp[(size_t)(row + 8) * D + col] = __floats2half2_rn(v[2], v[3]);
        }
}

// ---------------------------------------------------------------------------
// Kernel 4: out = (R @ Wo^T) * out_scale   (float output)
// ---------------------------------------------------------------------------
__global__ __launch_bounds__(256, 2) void out_gemm(
    const float* __restrict__ out_scale,
    float* __restrict__ out)
{
    GEMM_PROLOGUE();
    const int row0 = blockIdx.y * 128, col0 = blockIdx.x * 128;
    const __half* A = g_r + (size_t)row0 * D;
    const __half* B = g_wh + 3 * WN + (size_t)col0 * D;

    gemm_core(A, D, B, D, D / 32, acc, sb, tid, wm, wn, offA, offB);

    const float sc = *out_scale;
    float* Cp = out + (size_t)row0 * D + col0;
#pragma unroll
    for (int mi = 0; mi < 4; mi++)
#pragma unroll
        for (int ni = 0; ni < 4; ni++) {
            int row = wm + mi * 16 + g;
            int col = wn + ni * 8 + 2 * c;
            const float* v = acc[mi * 4 + ni];
            *(float2*)&Cp[(size_t)row * D + col] = make_float2(v[0] * sc, v[1] * sc);
            *(float2*)&Cp[(size_t)(row + 8) * D + col] = make_float2(v[2] * sc, v[3] * sc);
        }
}

// ---------------------------------------------------------------------------
extern "C" void kernel_launch(void* const* d_in, const int* in_sizes, int n_in,
                              void* d_out, int out_size)
{
    const float* x  = (const float*)d_in[0];
    const float* Wq = (const float*)d_in[1];
    const float* Wk = (const float*)d_in[2];
    const float* Wv = (const float*)d_in[3];
    const float* Wo = (const float*)d_in[4];
    const float* dl = (const float*)d_in[5];
    const float* os = (const float*)d_in[6];
    float* out = (float*)d_out;

    cudaFuncSetAttribute(qkv_gemm,    cudaFuncAttributeMaxDynamicSharedMemorySize, SMEM_BYTES);
    cudaFuncSetAttribute(scores_gemm, cudaFuncAttributeMaxDynamicSharedMemorySize, SMEM_BYTES);
    cudaFuncSetAttribute(retrv_gemm,  cudaFuncAttributeMaxDynamicSharedMemorySize, SMEM_BYTES);
    cudaFuncSetAttribute(out_gemm,    cudaFuncAttributeMaxDynamicSharedMemorySize, SMEM_BYTES);

    prep<<<(XN + 4 * WN) / (8 * 256), 256>>>(x, Wq, Wk, Wv, Wo);
    dim3 blk(256);
    qkv_gemm   <<<dim3(4, MTOT / 128, 3), blk, SMEM_BYTES>>>();
    scores_gemm<<<dim3(WKEYS / 128, BATCH * NQC), blk, SMEM_BYTES>>>(dl);
    retrv_gemm <<<dim3(4, BATCH * NQC), blk, SMEM_BYTES>>>();
    out_gemm   <<<dim3(4, MTOT / 128), blk, SMEM_BYTES>>>(os, out);
}